// round 6
// baseline (speedup 1.0000x reference)
#include <cuda_runtime.h>
#include <cuda_bf16.h>
#include <math.h>

#define NE 2048
#define NP 32768

// ---------------- static device scratch ----------------
__device__ float g_U[NE * 64];
__device__ float g_V[NE * 64];
__device__ float g_R[NP * 16];
__device__ float4 g_off4[NP * 4];     // per-pair 4 rows of -sgn * R_ji^T R_p
__device__ float g_lvals[NP];
__device__ float g_diag[NE * 16];
__device__ float g_Dinv[NE * 16];
__device__ float4 g_Z4[NE * 64];      // (n, f) -> {z0,z1,z2,z3}
__device__ float g_Xcol[NE * 64];

// ---------------- K0: U = ef@W1[:64]+b1 ; V = ef@W1[64:] ----------------
// grid 2048, block 128: one node, split-k (s = tid>>6 owns 32 k's)
__global__ void k_uv(const float* __restrict__ ef, const float* __restrict__ W1,
                     const float* __restrict__ b1) {
    int n = blockIdx.x;
    int tid = threadIdx.x;
    int f = tid & 63, s = tid >> 6;
    __shared__ float efs[64];
    __shared__ float up[2][64];
    __shared__ float vp[2][64];
    if (s == 0) efs[f] = ef[n * 64 + f];
    __syncthreads();
    float u = 0.f, v = 0.f;
    int k0 = 32 * s;
    #pragma unroll 8
    for (int k = k0; k < k0 + 32; k++) {
        float x = efs[k];
        u = fmaf(x, W1[k * 64 + f], u);
        v = fmaf(x, W1[(64 + k) * 64 + f], v);
    }
    up[s][f] = u;
    vp[s][f] = v;
    __syncthreads();
    if (s == 0) g_U[n * 64 + f] = up[0][f] + up[1][f] + b1[f];
    else        g_V[n * 64 + f] = vp[0][f] + vp[1][f];
}

// ---------------- K1: per-pair MLP tail -> R, plus L1 gather ------------
// grid 1024, block 256: 8 warps x 4 pairs each
__global__ void k_pair(const float* __restrict__ L1,
                       const float* __restrict__ W2, const float* __restrict__ b2,
                       const float* __restrict__ W3, const float* __restrict__ b3,
                       const int* __restrict__ eidx) {
    __shared__ float W2T[32][68];   // W2T[out][k], padded for LDS.128
    __shared__ float W3T[16][36];   // W3T[out][k]
    __shared__ float b2s[32], b3s[16];
    __shared__ float insh[8][96];
    int tid = threadIdx.x;
    for (int i = tid; i < 64 * 32; i += 256) {
        int k = i >> 5, o = i & 31;
        W2T[o][k] = W2[i];
    }
    for (int i = tid; i < 32 * 16; i += 256) {
        int k = i >> 4, o = i & 15;
        W3T[o][k] = W3[i];
    }
    if (tid < 32) b2s[tid] = b2[tid];
    if (tid < 16) b3s[tid] = b3[tid];
    __syncthreads();
    int w = tid >> 5, lane = tid & 31;
    int gw = blockIdx.x * 8 + w;            // 8192 warps, 4 pairs each
    int o = 2 * lane;
    #pragma unroll
    for (int pi = 0; pi < 4; pi++) {
        int p = gw * 4 + pi;
        int ii = eidx[2 * p], jj = eidx[2 * p + 1];
        if (lane == 0) g_lvals[p] = L1[(size_t)ii * NE + jj];
        float2 uu = *(const float2*)&g_U[ii * 64 + o];
        float2 vv = *(const float2*)&g_V[jj * 64 + o];
        float2 hv;
        hv.x = fmaxf(uu.x + vv.x, 0.f);
        hv.y = fmaxf(uu.y + vv.y, 0.f);
        *(float2*)&insh[w][o] = hv;
        __syncwarp();
        // layer 2: 64 -> 32
        float c = b2s[lane];
        #pragma unroll
        for (int k = 0; k < 64; k += 4) {
            float4 hh = *(const float4*)&insh[w][k];
            float4 ww = *(const float4*)&W2T[lane][k];
            c = fmaf(hh.x, ww.x, c);
            c = fmaf(hh.y, ww.y, c);
            c = fmaf(hh.z, ww.z, c);
            c = fmaf(hh.w, ww.w, c);
        }
        c = fmaxf(c, 0.f);
        insh[w][64 + lane] = c;
        __syncwarp();
        // layer 3: 32 -> 16 (no relu)
        if (lane < 16) {
            float r = b3s[lane];
            #pragma unroll
            for (int k = 0; k < 32; k += 4) {
                float4 hh = *(const float4*)&insh[w][64 + k];
                float4 ww = *(const float4*)&W3T[lane][k];
                r = fmaf(hh.x, ww.x, r);
                r = fmaf(hh.y, ww.y, r);
                r = fmaf(hh.z, ww.z, r);
                r = fmaf(hh.w, ww.w, r);
            }
            g_R[p * 16 + lane] = r;
        }
        __syncwarp();
    }
}

// ---------------- K2: diag + Jacobi Dinv + off blocks + Xt/Z/Xcol -------
// block = 256 threads, 8 nodes (=128 pairs) per block, grid 256
__global__ void k_mid(const float* __restrict__ X, const float* __restrict__ Ws1,
                      const float* __restrict__ Ws2, const int* __restrict__ jiidx) {
    __shared__ float sDb[8][16];
    __shared__ float sDinv[8][16];
    __shared__ float Ysh[8][4][64];
    int tid = threadIdx.x;
    int w = tid >> 5, lane = tid & 31;
    int node = blockIdx.x * 8 + w;

    // phase A: diag = segment-sum over 16 contiguous pairs (warp per node)
    float Fm[16];
    #pragma unroll
    for (int x = 0; x < 16; x++) Fm[x] = 0.f;
    if (lane < 16) {
        int p = node * 16 + lane;
        float4 r0 = *(const float4*)&g_R[p * 16];
        float4 r1 = *(const float4*)&g_R[p * 16 + 4];
        float4 r2 = *(const float4*)&g_R[p * 16 + 8];
        float4 r3 = *(const float4*)&g_R[p * 16 + 12];
        float Rv[16] = {r0.x, r0.y, r0.z, r0.w, r1.x, r1.y, r1.z, r1.w,
                        r2.x, r2.y, r2.z, r2.w, r3.x, r3.y, r3.z, r3.w};
        #pragma unroll
        for (int a = 0; a < 4; a++)
            #pragma unroll
            for (int b = 0; b < 4; b++) {
                float s = 0.f;
                #pragma unroll
                for (int c = 0; c < 4; c++) s = fmaf(Rv[c * 4 + a], Rv[c * 4 + b], s);
                Fm[a * 4 + b] = s;
            }
    }
    #pragma unroll
    for (int x = 0; x < 16; x++) {
        Fm[x] += __shfl_down_sync(0xffffffffu, Fm[x], 8);
        Fm[x] += __shfl_down_sync(0xffffffffu, Fm[x], 4);
        Fm[x] += __shfl_down_sync(0xffffffffu, Fm[x], 2);
        Fm[x] += __shfl_down_sync(0xffffffffu, Fm[x], 1);
    }
    if (lane == 0) {
        #pragma unroll
        for (int x = 0; x < 16; x++) { sDb[w][x] = Fm[x]; g_diag[node * 16 + x] = Fm[x]; }
    }
    __syncthreads();

    // phase B: threads 0-127 compute off blocks; threads 128-135 run Jacobi
    if (tid < 128) {
        int p = blockIdx.x * 128 + tid;
        int jp = jiidx[p];
        float l = g_lvals[p];
        float msg = (l > 0.f) ? -1.f : ((l < 0.f) ? 1.f : 0.f);  // -sign
        float4 a0 = *(const float4*)&g_R[jp * 16];
        float4 a1 = *(const float4*)&g_R[jp * 16 + 4];
        float4 a2 = *(const float4*)&g_R[jp * 16 + 8];
        float4 a3 = *(const float4*)&g_R[jp * 16 + 12];
        float4 b0 = *(const float4*)&g_R[p * 16];
        float4 b1v = *(const float4*)&g_R[p * 16 + 4];
        float4 b2v = *(const float4*)&g_R[p * 16 + 8];
        float4 b3v = *(const float4*)&g_R[p * 16 + 12];
        float Ra[16] = {a0.x, a0.y, a0.z, a0.w, a1.x, a1.y, a1.z, a1.w,
                        a2.x, a2.y, a2.z, a2.w, a3.x, a3.y, a3.z, a3.w};
        float Rb[16] = {b0.x, b0.y, b0.z, b0.w, b1v.x, b1v.y, b1v.z, b1v.w,
                        b2v.x, b2v.y, b2v.z, b2v.w, b3v.x, b3v.y, b3v.z, b3v.w};
        #pragma unroll
        for (int a = 0; a < 4; a++) {
            float4 row;
            float* rp = (float*)&row;
            #pragma unroll
            for (int b = 0; b < 4; b++) {
                float m = 0.f;
                #pragma unroll
                for (int c = 0; c < 4; c++) m = fmaf(Ra[c * 4 + a], Rb[c * 4 + b], m);
                rp[b] = msg * m;
            }
            g_off4[p * 4 + a] = row;
        }
    } else if (tid < 136) {
        int nl = tid - 128;
        const float eps = 1e-4f;
        float A[4][4], V[4][4];
        #pragma unroll
        for (int a = 0; a < 4; a++)
            #pragma unroll
            for (int b = 0; b < 4; b++) {
                A[a][b] = 0.5f * (sDb[nl][a * 4 + b] + sDb[nl][b * 4 + a]);
                V[a][b] = (a == b) ? 1.f : 0.f;
            }
        #pragma unroll
        for (int a = 0; a < 4; a++) A[a][a] += eps;
        const int PI[6] = {0, 0, 0, 1, 1, 2};
        const int QI[6] = {1, 2, 3, 2, 3, 3};
        #pragma unroll
        for (int sweep = 0; sweep < 6; sweep++) {
            #pragma unroll
            for (int r = 0; r < 6; r++) {
                int p = PI[r], q = QI[r];
                float apq = A[p][q];
                if (fabsf(apq) > 1e-20f) {
                    float theta = (A[q][q] - A[p][p]) / (2.f * apq);
                    float t = copysignf(1.f, theta) / (fabsf(theta) + sqrtf(theta * theta + 1.f));
                    float cth = rsqrtf(t * t + 1.f);
                    float sth = t * cth;
                    float app = A[p][p], aqq = A[q][q];
                    A[p][p] = app - t * apq;
                    A[q][q] = aqq + t * apq;
                    A[p][q] = 0.f; A[q][p] = 0.f;
                    #pragma unroll
                    for (int k = 0; k < 4; k++) {
                        if (k != p && k != q) {
                            float akp = A[k][p], akq = A[k][q];
                            A[k][p] = cth * akp - sth * akq; A[p][k] = A[k][p];
                            A[k][q] = sth * akp + cth * akq; A[q][k] = A[k][q];
                        }
                    }
                    #pragma unroll
                    for (int k = 0; k < 4; k++) {
                        float vkp = V[k][p], vkq = V[k][q];
                        V[k][p] = cth * vkp - sth * vkq;
                        V[k][q] = sth * vkp + cth * vkq;
                    }
                }
            }
        }
        float invs[4];
        #pragma unroll
        for (int k = 0; k < 4; k++) invs[k] = rsqrtf(fmaxf(A[k][k], eps));
        int gnode = blockIdx.x * 8 + nl;
        #pragma unroll
        for (int a = 0; a < 4; a++)
            #pragma unroll
            for (int b = 0; b < 4; b++) {
                float s = 0.f;
                #pragma unroll
                for (int k = 0; k < 4; k++) s = fmaf(V[a][k] * invs[k], V[b][k], s);
                sDinv[nl][a * 4 + b] = s;
                g_Dinv[gnode * 16 + a * 4 + b] = s;
            }
    }
    __syncthreads();

    // phase C: X_t = (Ws1 . Xr) @ Ws2 ; Z = Dinv @ X_t ; Xcol (8 nodes x 64f)
    #pragma unroll
    for (int it = 0; it < 2; it++) {
        int idx = tid + it * 256;
        int nl = idx >> 6, f = idx & 63;
        int n = blockIdx.x * 8 + nl;
        float xr[4];
        #pragma unroll
        for (int b = 0; b < 4; b++) xr[b] = X[(4 * n + b) * 64 + f];
        g_Xcol[n * 64 + f] = 0.25f * (xr[0] + xr[1] + xr[2] + xr[3]);
        #pragma unroll
        for (int a = 0; a < 4; a++) {
            float y = 0.f;
            #pragma unroll
            for (int b = 0; b < 4; b++) y = fmaf(Ws1[a * 4 + b], xr[b], y);
            Ysh[nl][a][f] = y;
        }
    }
    __syncthreads();
    #pragma unroll
    for (int it = 0; it < 2; it++) {
        int idx = tid + it * 256;
        int nl = idx >> 6, f = idx & 63;
        int n = blockIdx.x * 8 + nl;
        float xt[4] = {0.f, 0.f, 0.f, 0.f};
        #pragma unroll 4
        for (int g = 0; g < 64; g++) {
            float w2 = Ws2[g * 64 + f];
            #pragma unroll
            for (int a = 0; a < 4; a++) xt[a] = fmaf(Ysh[nl][a][g], w2, xt[a]);
        }
        float dv[16];
        #pragma unroll
        for (int x = 0; x < 16; x++) dv[x] = sDinv[nl][x];
        float4 z;
        z.x = fmaf(dv[0], xt[0], fmaf(dv[1], xt[1], fmaf(dv[2], xt[2], dv[3] * xt[3])));
        z.y = fmaf(dv[4], xt[0], fmaf(dv[5], xt[1], fmaf(dv[6], xt[2], dv[7] * xt[3])));
        z.z = fmaf(dv[8], xt[0], fmaf(dv[9], xt[1], fmaf(dv[10], xt[2], dv[11] * xt[3])));
        z.w = fmaf(dv[12], xt[0], fmaf(dv[13], xt[1], fmaf(dv[14], xt[2], dv[15] * xt[3])));
        g_Z4[n * 64 + f] = z;
    }
}

// ---------------- K3: hodge + sheaf + residual + output -----------------
// grid 2048, block 256 (a-major): thread (a = tid>>6, f = tid&63) owns
// output row 4i+a, feature f.
__global__ void k_out(const int* __restrict__ eidx, const float* __restrict__ Wh,
                      const float* __restrict__ X, const float* __restrict__ resW,
                      const float* __restrict__ resb, const float* __restrict__ alpha,
                      const float* __restrict__ beta, float* __restrict__ out) {
    int i = blockIdx.x;
    int tid = threadIdx.x;
    int f = tid & 63, a = tid >> 6;
    __shared__ float4 offs4[64];       // 16 neighbors x 4 rows
    __shared__ float Xsh[4][64];
    __shared__ float hpart[4][64];
    __shared__ float accsh[4][64];
    __shared__ float hrow[64];
    __shared__ int jsh[16];
    __shared__ float lvsh[16];

    // stage
    Xsh[a][f] = X[(4 * i + a) * 64 + f];
    if (a == 0) offs4[f] = g_off4[i * 64 + f];
    if (tid < 16) {
        int pp = 16 * i + tid;
        jsh[tid] = eidx[2 * pp + 1];
        lvsh[tid] = fabsf(g_lvals[pp]);
    }
    __syncthreads();

    // hodge gather: a-group handles neighbors 4a..4a+3
    float sum = 0.f;
    #pragma unroll
    for (int p = 0; p < 16; p++) sum += lvsh[p];
    float inv = 1.f / (sum + 1e-8f);
    float hacc = (a == 0) ? g_Xcol[i * 64 + f] : 0.f;
    #pragma unroll
    for (int p = 0; p < 4; p++) {
        int pp = 4 * a + p;
        hacc = fmaf(lvsh[pp] * inv, g_Xcol[jsh[pp] * 64 + f], hacc);
    }
    hpart[a][f] = hacc;

    // sheaf row a: diag_i[a,:] Z_i + sum_k off_k[a,:] Z_jk
    float4 zi = g_Z4[i * 64 + f];
    float4 dg = *(const float4*)&g_diag[i * 16 + 4 * a];
    float acc = fmaf(dg.x, zi.x, fmaf(dg.y, zi.y, fmaf(dg.z, zi.z, dg.w * zi.w)));
    #pragma unroll
    for (int k = 0; k < 16; k++) {
        float4 zj = g_Z4[jsh[k] * 64 + f];
        float4 o = offs4[k * 4 + a];
        acc = fmaf(o.x, zj.x, fmaf(o.y, zj.y, fmaf(o.z, zj.z, fmaf(o.w, zj.w, acc))));
    }
    accsh[a][f] = acc;
    __syncthreads();

    // Dinv apply row a
    float4 dv = *(const float4*)&g_Dinv[i * 16 + 4 * a];
    float sh = fmaf(dv.x, accsh[0][f],
               fmaf(dv.y, accsh[1][f],
               fmaf(dv.z, accsh[2][f], dv.w * accsh[3][f])));

    // reduce hodge partials (one a-group) while others proceed to residual
    if (a == 0) hrow[f] = hpart[0][f] + hpart[1][f] + hpart[2][f] + hpart[3][f];

    // residual row a
    float r = resb[f];
    #pragma unroll 8
    for (int k = 0; k < 64; k++)
        r = fmaf(Xsh[a][k], resW[k * 64 + f], r);
    __syncthreads();

    // hodge matmul (redundant across a; FMA pipe has headroom)
    float h = 0.f;
    #pragma unroll 8
    for (int g = 0; g < 64; g++)
        h = fmaf(hrow[g], Wh[g * 64 + f], h);

    float sa = 1.f / (1.f + expf(-alpha[0]));
    float sb = 1.f / (1.f + expf(-beta[0]));
    float e = (sh > 0.f) ? sh : expm1f(sh);
    out[(4 * i + a) * 64 + f] = r - sa * h - sb * e;
}

extern "C" void kernel_launch(void* const* d_in, const int* in_sizes, int n_in,
                              void* d_out, int out_size) {
    const float* ef    = (const float*)d_in[0];
    const float* L1    = (const float*)d_in[1];
    const float* X     = (const float*)d_in[2];
    const float* W1    = (const float*)d_in[3];
    const float* b1    = (const float*)d_in[4];
    const float* W2    = (const float*)d_in[5];
    const float* b2    = (const float*)d_in[6];
    const float* W3    = (const float*)d_in[7];
    const float* b3    = (const float*)d_in[8];
    const float* Wh    = (const float*)d_in[9];
    const float* Ws1   = (const float*)d_in[10];
    const float* Ws2   = (const float*)d_in[11];
    const float* resW  = (const float*)d_in[12];
    const float* resb  = (const float*)d_in[13];
    const float* alpha = (const float*)d_in[14];
    const float* beta  = (const float*)d_in[15];
    const int*   eidx  = (const int*)d_in[16];
    const int*   jiidx = (const int*)d_in[17];
    float* out = (float*)d_out;

    k_uv<<<2048, 128>>>(ef, W1, b1);
    k_pair<<<1024, 256>>>(L1, W2, b2, W3, b3, eidx);
    k_mid<<<256, 256>>>(X, Ws1, Ws2, jiidx);
    k_out<<<2048, 256>>>(eidx, Wh, X, resW, resb, alpha, beta, out);
}

// round 7
// speedup vs baseline: 1.1273x; 1.1273x over previous
#include <cuda_runtime.h>
#include <cuda_bf16.h>
#include <math.h>

#define NE 2048
#define NP 32768

// ---------------- static device scratch ----------------
__device__ float g_U[NE * 64];
__device__ float g_V[NE * 64];
__device__ float g_R[NP * 16];
__device__ float4 g_off4[NP * 4];     // per-pair 4 rows of -sgn * R_ji^T R_p
__device__ float g_lvals[NP];
__device__ float g_diag[NE * 16];
__device__ float g_Dinv[NE * 16];
__device__ float4 g_Z4[NE * 64];      // (n, f) -> {z0,z1,z2,z3}
__device__ float g_Xcol[NE * 64];

// ---------------- K0: U = ef@W1[:64]+b1 ; V = ef@W1[64:] ----------------
// grid 128, block 256; 16 nodes per block (4 passes) keeps W1 L1-hot
__global__ void k_uv(const float* __restrict__ ef, const float* __restrict__ W1,
                     const float* __restrict__ b1) {
    int nl = threadIdx.x >> 6, f = threadIdx.x & 63;
    __shared__ float efs[4][64];
    float bv = b1[f];
    for (int g = 0; g < 4; g++) {
        int n = blockIdx.x * 16 + g * 4 + nl;
        efs[nl][f] = ef[n * 64 + f];
        __syncthreads();
        float u = bv, v = 0.f;
        #pragma unroll 8
        for (int k = 0; k < 64; k++) {
            float x = efs[nl][k];
            u = fmaf(x, W1[k * 64 + f], u);
            v = fmaf(x, W1[(64 + k) * 64 + f], v);
        }
        g_U[n * 64 + f] = u;
        g_V[n * 64 + f] = v;
        __syncthreads();
    }
}

// ---------------- K1: per-pair MLP tail -> R, plus L1 gather ------------
__global__ void k_pair(const float* __restrict__ L1,
                       const float* __restrict__ W2, const float* __restrict__ b2,
                       const float* __restrict__ W3, const float* __restrict__ b3,
                       const int* __restrict__ eidx) {
    __shared__ float W2T[32][68];   // W2T[out][k], padded for LDS.128
    __shared__ float W3T[16][36];   // W3T[out][k]
    __shared__ float b2s[32], b3s[16];
    __shared__ float insh[8][96];
    int tid = threadIdx.x;
    for (int i = tid; i < 64 * 32; i += 256) {
        int k = i >> 5, o = i & 31;
        W2T[o][k] = W2[i];
    }
    for (int i = tid; i < 32 * 16; i += 256) {
        int k = i >> 4, o = i & 15;
        W3T[o][k] = W3[i];
    }
    if (tid < 32) b2s[tid] = b2[tid];
    if (tid < 16) b3s[tid] = b3[tid];
    __syncthreads();
    int w = tid >> 5, lane = tid & 31;
    int gw = blockIdx.x * 8 + w;            // 4096 warps, 8 pairs each
    int o = 2 * lane;
    #pragma unroll
    for (int pi = 0; pi < 8; pi++) {
        int p = gw * 8 + pi;
        int ii = eidx[2 * p], jj = eidx[2 * p + 1];
        if (lane == 0) g_lvals[p] = L1[(size_t)ii * NE + jj];
        float2 uu = *(const float2*)&g_U[ii * 64 + o];
        float2 vv = *(const float2*)&g_V[jj * 64 + o];
        float2 hv;
        hv.x = fmaxf(uu.x + vv.x, 0.f);
        hv.y = fmaxf(uu.y + vv.y, 0.f);
        *(float2*)&insh[w][o] = hv;
        __syncwarp();
        // layer 2: 64 -> 32
        float c = b2s[lane];
        #pragma unroll
        for (int k = 0; k < 64; k += 4) {
            float4 hh = *(const float4*)&insh[w][k];
            float4 ww = *(const float4*)&W2T[lane][k];
            c = fmaf(hh.x, ww.x, c);
            c = fmaf(hh.y, ww.y, c);
            c = fmaf(hh.z, ww.z, c);
            c = fmaf(hh.w, ww.w, c);
        }
        c = fmaxf(c, 0.f);
        insh[w][64 + lane] = c;
        __syncwarp();
        // layer 3: 32 -> 16 (no relu)
        if (lane < 16) {
            float r = b3s[lane];
            #pragma unroll
            for (int k = 0; k < 32; k += 4) {
                float4 hh = *(const float4*)&insh[w][64 + k];
                float4 ww = *(const float4*)&W3T[lane][k];
                r = fmaf(hh.x, ww.x, r);
                r = fmaf(hh.y, ww.y, r);
                r = fmaf(hh.z, ww.z, r);
                r = fmaf(hh.w, ww.w, r);
            }
            g_R[p * 16 + lane] = r;
        }
        __syncwarp();
    }
}

// ---------------- K2: diag + Jacobi Dinv + off blocks + Xt/Z/Xcol -------
// block = 256 threads, 8 nodes (=128 pairs) per block, grid 256
__global__ void k_mid(const float* __restrict__ X, const float* __restrict__ Ws1,
                      const float* __restrict__ Ws2, const int* __restrict__ jiidx) {
    __shared__ float sDb[8][16];
    __shared__ float sDinv[8][16];
    __shared__ float Ysh[8][4][64];
    int tid = threadIdx.x;
    int w = tid >> 5, lane = tid & 31;
    int node = blockIdx.x * 8 + w;

    // phase A: diag = segment-sum over 16 contiguous pairs (warp per node)
    float Fm[16];
    #pragma unroll
    for (int x = 0; x < 16; x++) Fm[x] = 0.f;
    if (lane < 16) {
        int p = node * 16 + lane;
        float4 r0 = *(const float4*)&g_R[p * 16];
        float4 r1 = *(const float4*)&g_R[p * 16 + 4];
        float4 r2 = *(const float4*)&g_R[p * 16 + 8];
        float4 r3 = *(const float4*)&g_R[p * 16 + 12];
        float Rv[16] = {r0.x, r0.y, r0.z, r0.w, r1.x, r1.y, r1.z, r1.w,
                        r2.x, r2.y, r2.z, r2.w, r3.x, r3.y, r3.z, r3.w};
        #pragma unroll
        for (int a = 0; a < 4; a++)
            #pragma unroll
            for (int b = 0; b < 4; b++) {
                float s = 0.f;
                #pragma unroll
                for (int c = 0; c < 4; c++) s = fmaf(Rv[c * 4 + a], Rv[c * 4 + b], s);
                Fm[a * 4 + b] = s;
            }
    }
    #pragma unroll
    for (int x = 0; x < 16; x++) {
        Fm[x] += __shfl_down_sync(0xffffffffu, Fm[x], 8);
        Fm[x] += __shfl_down_sync(0xffffffffu, Fm[x], 4);
        Fm[x] += __shfl_down_sync(0xffffffffu, Fm[x], 2);
        Fm[x] += __shfl_down_sync(0xffffffffu, Fm[x], 1);
    }
    if (lane == 0) {
        #pragma unroll
        for (int x = 0; x < 16; x++) { sDb[w][x] = Fm[x]; g_diag[node * 16 + x] = Fm[x]; }
    }
    __syncthreads();

    // phase B: threads 0-127 compute off blocks; threads 128-135 run Jacobi
    if (tid < 128) {
        int p = blockIdx.x * 128 + tid;
        int jp = jiidx[p];
        float l = g_lvals[p];
        float msg = (l > 0.f) ? -1.f : ((l < 0.f) ? 1.f : 0.f);  // -sign
        float4 a0 = *(const float4*)&g_R[jp * 16];
        float4 a1 = *(const float4*)&g_R[jp * 16 + 4];
        float4 a2 = *(const float4*)&g_R[jp * 16 + 8];
        float4 a3 = *(const float4*)&g_R[jp * 16 + 12];
        float4 b0 = *(const float4*)&g_R[p * 16];
        float4 b1v = *(const float4*)&g_R[p * 16 + 4];
        float4 b2v = *(const float4*)&g_R[p * 16 + 8];
        float4 b3v = *(const float4*)&g_R[p * 16 + 12];
        float Ra[16] = {a0.x, a0.y, a0.z, a0.w, a1.x, a1.y, a1.z, a1.w,
                        a2.x, a2.y, a2.z, a2.w, a3.x, a3.y, a3.z, a3.w};
        float Rb[16] = {b0.x, b0.y, b0.z, b0.w, b1v.x, b1v.y, b1v.z, b1v.w,
                        b2v.x, b2v.y, b2v.z, b2v.w, b3v.x, b3v.y, b3v.z, b3v.w};
        #pragma unroll
        for (int a = 0; a < 4; a++) {
            float4 row;
            float* rp = (float*)&row;
            #pragma unroll
            for (int b = 0; b < 4; b++) {
                float m = 0.f;
                #pragma unroll
                for (int c = 0; c < 4; c++) m = fmaf(Ra[c * 4 + a], Rb[c * 4 + b], m);
                rp[b] = msg * m;
            }
            g_off4[p * 4 + a] = row;
        }
    } else if (tid < 136) {
        int nl = tid - 128;
        const float eps = 1e-4f;
        float A[4][4], V[4][4];
        #pragma unroll
        for (int a = 0; a < 4; a++)
            #pragma unroll
            for (int b = 0; b < 4; b++) {
                A[a][b] = 0.5f * (sDb[nl][a * 4 + b] + sDb[nl][b * 4 + a]);
                V[a][b] = (a == b) ? 1.f : 0.f;
            }
        #pragma unroll
        for (int a = 0; a < 4; a++) A[a][a] += eps;
        const int PI[6] = {0, 0, 0, 1, 1, 2};
        const int QI[6] = {1, 2, 3, 2, 3, 3};
        #pragma unroll
        for (int sweep = 0; sweep < 6; sweep++) {
            #pragma unroll
            for (int r = 0; r < 6; r++) {
                int p = PI[r], q = QI[r];
                float apq = A[p][q];
                if (fabsf(apq) > 1e-20f) {
                    float theta = (A[q][q] - A[p][p]) / (2.f * apq);
                    float t = copysignf(1.f, theta) / (fabsf(theta) + sqrtf(theta * theta + 1.f));
                    float cth = rsqrtf(t * t + 1.f);
                    float sth = t * cth;
                    float app = A[p][p], aqq = A[q][q];
                    A[p][p] = app - t * apq;
                    A[q][q] = aqq + t * apq;
                    A[p][q] = 0.f; A[q][p] = 0.f;
                    #pragma unroll
                    for (int k = 0; k < 4; k++) {
                        if (k != p && k != q) {
                            float akp = A[k][p], akq = A[k][q];
                            A[k][p] = cth * akp - sth * akq; A[p][k] = A[k][p];
                            A[k][q] = sth * akp + cth * akq; A[q][k] = A[k][q];
                        }
                    }
                    #pragma unroll
                    for (int k = 0; k < 4; k++) {
                        float vkp = V[k][p], vkq = V[k][q];
                        V[k][p] = cth * vkp - sth * vkq;
                        V[k][q] = sth * vkp + cth * vkq;
                    }
                }
            }
        }
        float invs[4];
        #pragma unroll
        for (int k = 0; k < 4; k++) invs[k] = rsqrtf(fmaxf(A[k][k], eps));
        int gnode = blockIdx.x * 8 + nl;
        #pragma unroll
        for (int a = 0; a < 4; a++)
            #pragma unroll
            for (int b = 0; b < 4; b++) {
                float s = 0.f;
                #pragma unroll
                for (int k = 0; k < 4; k++) s = fmaf(V[a][k] * invs[k], V[b][k], s);
                sDinv[nl][a * 4 + b] = s;
                g_Dinv[gnode * 16 + a * 4 + b] = s;
            }
    }
    __syncthreads();

    // phase C: X_t = (Ws1 . Xr) @ Ws2 ; Z = Dinv @ X_t ; Xcol (8 nodes x 64f)
    #pragma unroll
    for (int it = 0; it < 2; it++) {
        int idx = tid + it * 256;
        int nl = idx >> 6, f = idx & 63;
        int n = blockIdx.x * 8 + nl;
        float xr[4];
        #pragma unroll
        for (int b = 0; b < 4; b++) xr[b] = X[(4 * n + b) * 64 + f];
        g_Xcol[n * 64 + f] = 0.25f * (xr[0] + xr[1] + xr[2] + xr[3]);
        #pragma unroll
        for (int a = 0; a < 4; a++) {
            float y = 0.f;
            #pragma unroll
            for (int b = 0; b < 4; b++) y = fmaf(Ws1[a * 4 + b], xr[b], y);
            Ysh[nl][a][f] = y;
        }
    }
    __syncthreads();
    #pragma unroll
    for (int it = 0; it < 2; it++) {
        int idx = tid + it * 256;
        int nl = idx >> 6, f = idx & 63;
        int n = blockIdx.x * 8 + nl;
        float xt[4] = {0.f, 0.f, 0.f, 0.f};
        #pragma unroll 4
        for (int g = 0; g < 64; g++) {
            float w2 = Ws2[g * 64 + f];
            #pragma unroll
            for (int a = 0; a < 4; a++) xt[a] = fmaf(Ysh[nl][a][g], w2, xt[a]);
        }
        float dv[16];
        #pragma unroll
        for (int x = 0; x < 16; x++) dv[x] = sDinv[nl][x];
        float4 z;
        z.x = fmaf(dv[0], xt[0], fmaf(dv[1], xt[1], fmaf(dv[2], xt[2], dv[3] * xt[3])));
        z.y = fmaf(dv[4], xt[0], fmaf(dv[5], xt[1], fmaf(dv[6], xt[2], dv[7] * xt[3])));
        z.z = fmaf(dv[8], xt[0], fmaf(dv[9], xt[1], fmaf(dv[10], xt[2], dv[11] * xt[3])));
        z.w = fmaf(dv[12], xt[0], fmaf(dv[13], xt[1], fmaf(dv[14], xt[2], dv[15] * xt[3])));
        g_Z4[n * 64 + f] = z;
    }
}

// ---------------- K3: hodge + sheaf + residual + output -----------------
// grid 512, block 256, 4 nodes/block. Neighbors are banded (j = i±1..8 mod NE),
// so a 20-row window of Z4/Xcol covers all gathers for the block -> stage it
// in shared once, gathers become conflict-free LDS.
__global__ void k_out(const int* __restrict__ eidx, const float* __restrict__ Wh,
                      const float* __restrict__ X, const float* __restrict__ resW,
                      const float* __restrict__ resb, const float* __restrict__ alpha,
                      const float* __restrict__ beta, float* __restrict__ out) {
    int tid = threadIdx.x;
    int nl = tid >> 6, f = tid & 63;
    int i0 = blockIdx.x * 4;
    int i = i0 + nl;
    __shared__ float4 Z4sh[20][64];      // rows i0-8 .. i0+11 (mod NE)
    __shared__ float Xcolsh[20][64];
    __shared__ float4 offs4[4][64];
    __shared__ float Xsh[4][4][64];
    __shared__ float hp[4][64];
    __shared__ int jrel[4][16];
    __shared__ float lvsh[4][16];

    // stage the banded window (coalesced LDG.128 / LDG.32)
    #pragma unroll
    for (int t = 0; t < 5; t++) {
        int idx = tid + t * 256;          // 0..1279
        int row = idx >> 6, ff = idx & 63;
        int src = (i0 - 8 + row) & (NE - 1);
        Z4sh[row][ff] = g_Z4[src * 64 + ff];
        Xcolsh[row][ff] = g_Xcol[src * 64 + ff];
    }
    #pragma unroll
    for (int b = 0; b < 4; b++) Xsh[nl][b][f] = X[(4 * i + b) * 64 + f];
    offs4[nl][f] = g_off4[i * 64 + f];
    if (f < 16) {
        int pp = 16 * i + f;
        int j = eidx[2 * pp + 1];
        jrel[nl][f] = (j - i0 + 8) & (NE - 1);   // in [0, 20)
        lvsh[nl][f] = fabsf(g_lvals[pp]);
    }
    __syncthreads();

    // hodge row part (all gathers from shared)
    float s = 0.f;
    #pragma unroll
    for (int p = 0; p < 16; p++) s += lvsh[nl][p];
    float inv = 1.f / (s + 1e-8f);
    float acc = Xcolsh[8 + nl][f];
    #pragma unroll
    for (int p = 0; p < 16; p++)
        acc = fmaf(lvsh[nl][p] * inv, Xcolsh[jrel[nl][p]][f], acc);
    hp[nl][f] = acc;

    // sheaf: diag_i Z_i + sum_k off_k Z_jk (Z from shared window)
    float4 zi = Z4sh[8 + nl][f];
    const float4* dgr = (const float4*)&g_diag[i * 16];
    float accs[4];
    #pragma unroll
    for (int a = 0; a < 4; a++) {
        float4 d = dgr[a];
        accs[a] = fmaf(d.x, zi.x, fmaf(d.y, zi.y, fmaf(d.z, zi.z, d.w * zi.w)));
    }
    #pragma unroll
    for (int k = 0; k < 16; k++) {
        float4 zj = Z4sh[jrel[nl][k]][f];
        #pragma unroll
        for (int a = 0; a < 4; a++) {
            float4 o = offs4[nl][k * 4 + a];
            accs[a] = fmaf(o.x, zj.x, fmaf(o.y, zj.y, fmaf(o.z, zj.z, fmaf(o.w, zj.w, accs[a]))));
        }
    }
    const float4* dvr = (const float4*)&g_Dinv[i * 16];
    float sh[4];
    #pragma unroll
    for (int a = 0; a < 4; a++) {
        float4 d = dvr[a];
        sh[a] = fmaf(d.x, accs[0], fmaf(d.y, accs[1], fmaf(d.z, accs[2], d.w * accs[3])));
    }

    __syncthreads();
    // hodge matmul
    float h = 0.f;
    #pragma unroll 4
    for (int g = 0; g < 64; g++) h = fmaf(hp[nl][g], Wh[g * 64 + f], h);

    // residual matmul
    float r[4];
    float bb = resb[f];
    #pragma unroll
    for (int b = 0; b < 4; b++) r[b] = bb;
    #pragma unroll 4
    for (int k = 0; k < 64; k++) {
        float w = resW[k * 64 + f];
        #pragma unroll
        for (int b = 0; b < 4; b++) r[b] = fmaf(Xsh[nl][b][k], w, r[b]);
    }

    float sa = 1.f / (1.f + expf(-alpha[0]));
    float sb = 1.f / (1.f + expf(-beta[0]));
    #pragma unroll
    for (int b = 0; b < 4; b++) {
        float e = (sh[b] > 0.f) ? sh[b] : expm1f(sh[b]);
        out[(4 * i + b) * 64 + f] = r[b] - sa * h - sb * e;
    }
}

extern "C" void kernel_launch(void* const* d_in, const int* in_sizes, int n_in,
                              void* d_out, int out_size) {
    const float* ef    = (const float*)d_in[0];
    const float* L1    = (const float*)d_in[1];
    const float* X     = (const float*)d_in[2];
    const float* W1    = (const float*)d_in[3];
    const float* b1    = (const float*)d_in[4];
    const float* W2    = (const float*)d_in[5];
    const float* b2    = (const float*)d_in[6];
    const float* W3    = (const float*)d_in[7];
    const float* b3    = (const float*)d_in[8];
    const float* Wh    = (const float*)d_in[9];
    const float* Ws1   = (const float*)d_in[10];
    const float* Ws2   = (const float*)d_in[11];
    const float* resW  = (const float*)d_in[12];
    const float* resb  = (const float*)d_in[13];
    const float* alpha = (const float*)d_in[14];
    const float* beta  = (const float*)d_in[15];
    const int*   eidx  = (const int*)d_in[16];
    const int*   jiidx = (const int*)d_in[17];
    float* out = (float*)d_out;

    k_uv<<<128, 256>>>(ef, W1, b1);
    k_pair<<<512, 256>>>(L1, W2, b2, W3, b3, eidx);
    k_mid<<<256, 256>>>(X, Ws1, Ws2, jiidx);
    k_out<<<512, 256>>>(eidx, Wh, X, resW, resb, alpha, beta, out);
}